// round 9
// baseline (speedup 1.0000x reference)
#include <cuda_runtime.h>
#include <cuda_bf16.h>
#include <math.h>
#include <stdint.h>

#define N_NODES 100000
#define N_EDGES 1600000
#define F_IN    512
#define HD      64
#define NH      8
#define C_OUT   40

typedef unsigned long long ull;

// ------------------------- scratch (device globals; no mallocs) -------------
__device__ float    g_h1  [N_NODES*HD];
__device__ float    g_agg1[N_NODES*HD];
__device__ float2   g_e1s [N_NODES*NH];    // (exp(as), exp(0.2 as)) per node,head
__device__ float2   g_e1d [N_NODES*NH];    // (exp(ad), exp(0.2 ad))
__device__ float    g_den1[N_NODES*NH];
__device__ float    g_h2  [N_NODES*C_OUT];
__device__ float    g_agg2[N_NODES*C_OUT];
__device__ float2   g_e2s [N_NODES];
__device__ float2   g_e2d [N_NODES];
__device__ float    g_den2[N_NODES];
__device__ float2   g_Wp2[32*40];                  // W2 k-pair interleave
__device__ __nv_bfloat16 g_W1thi[HD*F_IN];         // W1^T hi plane  [n][k]
__device__ __nv_bfloat16 g_W1tlo[HD*F_IN];         // W1^T lo plane  [n][k]

// ------------------------- helpers ------------------------------------------
__device__ __forceinline__ ull ffma2(ull a, ull b, ull c) {
    ull d;
    asm("fma.rn.f32x2 %0, %1, %2, %3;" : "=l"(d) : "l"(a), "l"(b), "l"(c));
    return d;
}
__device__ __forceinline__ float lo32(ull v){ return __uint_as_float((unsigned)(v & 0xffffffffull)); }
__device__ __forceinline__ float hi32(ull v){ return __uint_as_float((unsigned)(v >> 32)); }
__device__ __forceinline__ float elu1(float x){ return x > 0.f ? x : __expf(x) - 1.f; }
// edge exp via precomputed node factors: exp(lrelu(a+b))
__device__ __forceinline__ float edge_exp(float2 ea, float2 eb){
    float p = ea.x * eb.x;                 // exp(a)*exp(b) = exp(a+b)
    return p > 1.f ? p : ea.y * eb.y;      // else exp(0.2a)*exp(0.2b)
}
__device__ __forceinline__ uint32_t smem_u32(const void* p){
    uint32_t a;
    asm("{ .reg .u64 t; cvta.to.shared.u64 t, %1; cvt.u32.u64 %0, t; }" : "=r"(a) : "l"(p));
    return a;
}
__device__ __forceinline__ unsigned pack_bf16(__nv_bfloat16 a, __nv_bfloat16 b){
    return (unsigned)__bfloat16_as_ushort(a) | ((unsigned)__bfloat16_as_ushort(b) << 16);
}
__device__ __forceinline__ void ldsm4(unsigned* r, uint32_t addr){
    asm volatile("ldmatrix.sync.aligned.m8n8.x4.shared.b16 {%0,%1,%2,%3}, [%4];"
        : "=r"(r[0]), "=r"(r[1]), "=r"(r[2]), "=r"(r[3]) : "r"(addr));
}
__device__ __forceinline__ void mma16816(float* c, const unsigned* a, unsigned b0, unsigned b1){
    asm volatile("mma.sync.aligned.m16n8k16.row.col.f32.bf16.bf16.f32 "
        "{%0,%1,%2,%3}, {%4,%5,%6,%7}, {%8,%9}, {%0,%1,%2,%3};"
        : "+f"(c[0]), "+f"(c[1]), "+f"(c[2]), "+f"(c[3])
        : "r"(a[0]), "r"(a[1]), "r"(a[2]), "r"(a[3]), "r"(b0), "r"(b1));
}

// ------------------------- prep: W1 transpose+split, W2 interleave ----------
__global__ void k_prep(const float* __restrict__ W1, const float* __restrict__ W2){
    int i = blockIdx.x*blockDim.x + threadIdx.x;
    if (i < F_IN*HD){
        int k = i >> 6, n = i & 63;
        float v = W1[i];
        __nv_bfloat16 h = __float2bfloat16_rn(v);
        float lo = v - __bfloat162float(h);
        g_W1thi[n*F_IN + k] = h;
        g_W1tlo[n*F_IN + k] = __float2bfloat16_rn(lo);
    }
    if (i < 32*40){
        int kk = i / 40, c = i - kk*40;
        g_Wp2[i] = make_float2(W2[(2*kk)*40 + c], W2[(2*kk+1)*40 + c]);
    }
}

// ------------------------- GEMM1: mma.sync bf16 2-term split ----------------
__global__ void __launch_bounds__(256) k_gemm1(const float* __restrict__ x,
                                               const float* __restrict__ aw_s,
                                               const float* __restrict__ aw_d){
    __shared__ __align__(16) unsigned char sAhi[128*80];
    __shared__ __align__(16) unsigned char sAlo[128*80];
    __shared__ __align__(16) unsigned char sWhi[64*80];
    __shared__ __align__(16) unsigned char sWlo[64*80];

    int tid = threadIdx.x, w = tid >> 5, l = tid & 31;
    int mg = w >> 1, ng = w & 1;
    int row0 = blockIdx.x * 128;

    uint32_t aAhi = smem_u32(sAhi), aAlo = smem_u32(sAlo);
    uint32_t aWhi = smem_u32(sWhi), aWlo = smem_u32(sWlo);

    float acc[2][4][4];
    #pragma unroll
    for (int a=0;a<2;a++) for (int b=0;b<4;b++) for (int c=0;c<4;c++) acc[a][b][c]=0.f;

    for (int ch = 0; ch < 16; ++ch){
        int k0 = ch * 32;
        __syncthreads();
        #pragma unroll
        for (int j = 0; j < 4; ++j){
            int idx = tid + 256*j;
            int row = idx >> 3, kq = idx & 7;
            int gr = row0 + row;
            float4 v = make_float4(0.f,0.f,0.f,0.f);
            if (gr < N_NODES) v = *(const float4*)(x + (size_t)gr*F_IN + k0 + kq*4);
            __nv_bfloat16 h0=__float2bfloat16_rn(v.x), h1=__float2bfloat16_rn(v.y),
                          h2=__float2bfloat16_rn(v.z), h3=__float2bfloat16_rn(v.w);
            uint2 hp, lp;
            hp.x = pack_bf16(h0, h1); hp.y = pack_bf16(h2, h3);
            lp.x = pack_bf16(__float2bfloat16_rn(v.x - __bfloat162float(h0)),
                             __float2bfloat16_rn(v.y - __bfloat162float(h1)));
            lp.y = pack_bf16(__float2bfloat16_rn(v.z - __bfloat162float(h2)),
                             __float2bfloat16_rn(v.w - __bfloat162float(h3)));
            *(uint2*)(sAhi + row*80 + kq*8) = hp;
            *(uint2*)(sAlo + row*80 + kq*8) = lp;
        }
        #pragma unroll
        for (int j = 0; j < 2; ++j){
            int idx = tid + 256*j;
            int n = idx >> 3, kq = idx & 7;
            *(uint2*)(sWhi + n*80 + kq*8) = *(const uint2*)(g_W1thi + n*F_IN + k0 + kq*4);
            *(uint2*)(sWlo + n*80 + kq*8) = *(const uint2*)(g_W1tlo + n*F_IN + k0 + kq*4);
        }
        __syncthreads();
        int g = l >> 3, i = l & 7;
        #pragma unroll
        for (int ks = 0; ks < 2; ++ks){
            int kb = ks*32;
            unsigned ah[2][4], al[2][4], bh[2][4], bl[2][4];
            #pragma unroll
            for (int mt = 0; mt < 2; ++mt){
                int rl = mg*32 + mt*16 + i + ((g & 1) ? 8 : 0);
                int co = kb + ((g & 2) ? 16 : 0);
                ldsm4(ah[mt], aAhi + rl*80 + co);
                ldsm4(al[mt], aAlo + rl*80 + co);
            }
            #pragma unroll
            for (int np = 0; np < 2; ++np){
                int nl = ng*32 + np*16 + i + ((g & 2) ? 8 : 0);
                int co = kb + ((g & 1) ? 16 : 0);
                ldsm4(bh[np], aWhi + nl*80 + co);
                ldsm4(bl[np], aWlo + nl*80 + co);
            }
            #pragma unroll
            for (int mt = 0; mt < 2; ++mt)
                #pragma unroll
                for (int np = 0; np < 2; ++np){
                    mma16816(acc[mt][2*np],   ah[mt], bh[np][0], bh[np][1]);
                    mma16816(acc[mt][2*np+1], ah[mt], bh[np][2], bh[np][3]);
                    mma16816(acc[mt][2*np],   ah[mt], bl[np][0], bl[np][1]);
                    mma16816(acc[mt][2*np+1], ah[mt], bl[np][2], bl[np][3]);
                    mma16816(acc[mt][2*np],   al[mt], bh[np][0], bh[np][1]);
                    mma16816(acc[mt][2*np+1], al[mt], bh[np][2], bh[np][3]);
                }
        }
    }

    // ---- epilogue: h1, exp-factor tables, zero agg1/den1 ----
    int q = l & 3;
    #pragma unroll
    for (int mt = 0; mt < 2; ++mt)
        #pragma unroll
        for (int half = 0; half < 2; ++half){
            int gr = row0 + mg*32 + mt*16 + half*8 + (l >> 2);
            bool ok = gr < N_NODES;
            float hs[4], hd[4];
            #pragma unroll
            for (int nt = 0; nt < 4; ++nt){
                float c0 = acc[mt][nt][half*2], c1 = acc[mt][nt][half*2+1];
                if (ok){
                    int col = ng*32 + nt*8 + 2*q;
                    *(float2*)(g_h1  + gr*64 + col) = make_float2(c0, c1);
                    *(float2*)(g_agg1 + gr*64 + col) = make_float2(0.f, 0.f);
                }
                int head = 4*ng + nt;
                hs[nt] = c0*__ldg(aw_s + head*8 + 2*q) + c1*__ldg(aw_s + head*8 + 2*q + 1);
                hd[nt] = c0*__ldg(aw_d + head*8 + 2*q) + c1*__ldg(aw_d + head*8 + 2*q + 1);
            }
            #pragma unroll
            for (int nt = 0; nt < 4; ++nt){
                hs[nt] += __shfl_xor_sync(0xffffffffu, hs[nt], 1);
                hs[nt] += __shfl_xor_sync(0xffffffffu, hs[nt], 2);
                hd[nt] += __shfl_xor_sync(0xffffffffu, hd[nt], 1);
                hd[nt] += __shfl_xor_sync(0xffffffffu, hd[nt], 2);
            }
            if (ok){
                float vs = (q==0)?hs[0]:(q==1)?hs[1]:(q==2)?hs[2]:hs[3];
                float vd = (q==0)?hd[0]:(q==1)?hd[1]:(q==2)?hd[2]:hd[3];
                int slot = gr*8 + 4*ng + q;
                g_e1s [slot] = make_float2(__expf(vs), __expf(0.2f*vs));
                g_e1d [slot] = make_float2(__expf(vd), __expf(0.2f*vd));
                g_den1[slot] = 0.f;
            }
        }
}

// ------------------------- layer1 edge aggregate (E x 16 threads) -----------
__global__ void __launch_bounds__(256) k_eagg1(const int* __restrict__ ei){
    int t = blockIdx.x*blockDim.x + threadIdx.x;
    int e = t >> 4, c = t & 15;
    int lane = t & 31;
    int s = ei[e], d = ei[N_EDGES + e];
    int h = c >> 1;
    float ee = edge_exp(g_e1s[s*8 + h], g_e1d[d*8 + h]);
    float4 v = ((const float4*)g_h1)[s*16 + c];
    float4 m = make_float4(ee*v.x, ee*v.y, ee*v.z, ee*v.w);
    atomicAdd(((float4*)g_agg1) + d*16 + c, m);
    int b2 = (lane & 16) + (c & 8);
    float d0 = __shfl_sync(0xffffffffu, ee, b2 + 0);
    float d1 = __shfl_sync(0xffffffffu, ee, b2 + 2);
    float d2 = __shfl_sync(0xffffffffu, ee, b2 + 4);
    float d3 = __shfl_sync(0xffffffffu, ee, b2 + 6);
    if ((c & 7) == 0){
        float* dst = g_den1 + d*8 + ((c & 8) ? 4 : 0);
        atomicAdd((float4*)dst, make_float4(d0, d1, d2, d3));
    }
}

// ------------------------- GEMM2 (fin1 fused into loader) -------------------
__global__ void __launch_bounds__(256) k_gemm2(const float* __restrict__ aw_s,
                                               const float* __restrict__ aw_d,
                                               const float* __restrict__ b1){
    __shared__ float sx[64*64];
    int row0 = blockIdx.x * 64;
    int tid  = threadIdx.x;

    {
        float4 z = make_float4(0.f,0.f,0.f,0.f);
        float4* a4 = (float4*)(g_agg2 + (size_t)row0*40);
        #pragma unroll
        for (int j = tid; j < 640; j += 256){
            int row = row0 + j/10;
            if (row < N_NODES) a4[j] = z;
        }
        if (tid < 64 && row0 + tid < N_NODES) g_den2[row0 + tid] = 0.f;
    }

    // fused fin1: softmax-normalize + self-loop + bias + ELU while staging
    float4* s4 = (float4*)sx;
    #pragma unroll
    for (int i = 0; i < 4; ++i){
        int idx  = tid + 256*i;
        int grow = row0 + (idx >> 4);
        int c    = idx & 15, h = c >> 1;
        float4 v = make_float4(0.f,0.f,0.f,0.f);
        if (grow < N_NODES){
            float ws  = edge_exp(g_e1s[grow*8+h], g_e1d[grow*8+h]);   // self-loop
            float inv = 1.f / (g_den1[grow*8+h] + ws + 1e-16f);
            float4 a  = ((const float4*)g_agg1)[grow*16 + c];
            float4 hv = ((const float4*)g_h1)[grow*16 + c];
            float4 bb = ((const float4*)b1)[c];
            v.x = elu1((a.x + ws*hv.x)*inv + bb.x);
            v.y = elu1((a.y + ws*hv.y)*inv + bb.y);
            v.z = elu1((a.z + ws*hv.z)*inv + bb.z);
            v.w = elu1((a.w + ws*hv.w)*inv + bb.w);
        }
        s4[idx] = v;
    }
    __syncthreads();

    int w = tid >> 5, l = tid & 31;
    ull acc0[8], acc1[8];
    #pragma unroll
    for (int r = 0; r < 8; ++r){ acc0[r] = 0ull; acc1[r] = 0ull; }

    const ull* sb = (const ull*)sx;
    const ull* wp = (const ull*)g_Wp2;
    #pragma unroll 4
    for (int kk = 0; kk < 32; kk += 2){
        ull w0a = wp[kk*40 + l];
        ull w1a = (l < 8) ? wp[kk*40 + 32 + l] : 0ull;
        ull w0b = wp[(kk+1)*40 + l];
        ull w1b = (l < 8) ? wp[(kk+1)*40 + 32 + l] : 0ull;
        #pragma unroll
        for (int r = 0; r < 8; ++r){
            const ull* srow = sb + (8*w + r)*32;
            ulonglong2 xv = *(const ulonglong2*)(srow + kk);
            acc0[r] = ffma2(xv.x, w0a, acc0[r]);
            acc1[r] = ffma2(xv.x, w1a, acc1[r]);
            acc0[r] = ffma2(xv.y, w0b, acc0[r]);
            acc1[r] = ffma2(xv.y, w1b, acc1[r]);
        }
    }

    #pragma unroll
    for (int r = 0; r < 8; ++r){
        int row = row0 + 8*w + r;
        bool valid = row < N_NODES;
        float o0 = lo32(acc0[r]) + hi32(acc0[r]);
        float o1 = lo32(acc1[r]) + hi32(acc1[r]);
        if (valid){
            g_h2[row*40 + l] = o0;
            if (l < 8) g_h2[row*40 + 32 + l] = o1;
        }
        float ps = o0*aw_s[l] + ((l < 8) ? o1*aw_s[32+l] : 0.f);
        float pd = o0*aw_d[l] + ((l < 8) ? o1*aw_d[32+l] : 0.f);
        #pragma unroll
        for (int off = 16; off; off >>= 1){
            ps += __shfl_xor_sync(0xffffffffu, ps, off);
            pd += __shfl_xor_sync(0xffffffffu, pd, off);
        }
        if (l == 0 && valid){
            g_e2s[row] = make_float2(__expf(ps), __expf(0.2f*ps));
            g_e2d[row] = make_float2(__expf(pd), __expf(0.2f*pd));
        }
    }
}

// ------------------------- layer2 edge aggregate (E x 10 threads) -----------
__global__ void __launch_bounds__(320) k_eagg2(const int* __restrict__ ei){
    int t = blockIdx.x*320 + threadIdx.x;
    int e = t / 10, c = t - e*10;
    int s = ei[e], d = ei[N_EDGES + e];
    float ee = edge_exp(g_e2s[s], g_e2d[d]);
    float4 v = ((const float4*)g_h2)[s*10 + c];
    float4 m = make_float4(ee*v.x, ee*v.y, ee*v.z, ee*v.w);
    atomicAdd(((float4*)g_agg2) + d*10 + c, m);
    if (c == 0) atomicAdd(&g_den2[d], ee);
}

// ------------------------- layer2 finalize + log_softmax --------------------
__global__ void __launch_bounds__(256) k_fin2(const float* __restrict__ b2,
                                              float* __restrict__ out){
    int gid = blockIdx.x*blockDim.x + threadIdx.x;
    int n = gid >> 5, l = gid & 31;
    if (n >= N_NODES) return;
    float ws  = edge_exp(g_e2s[n], g_e2d[n]);
    float inv = 1.f / (g_den2[n] + ws + 1e-16f);
    float v0 = (g_agg2[n*40 + l] + ws*g_h2[n*40 + l])*inv + b2[l];
    float v1 = -INFINITY;
    if (l < 8)
        v1 = (g_agg2[n*40 + 32 + l] + ws*g_h2[n*40 + 32 + l])*inv + b2[32+l];
    float mx = fmaxf(v0, v1);
    #pragma unroll
    for (int off = 16; off; off >>= 1) mx = fmaxf(mx, __shfl_xor_sync(0xffffffffu, mx, off));
    float se = __expf(v0 - mx) + ((l < 8) ? __expf(v1 - mx) : 0.f);
    #pragma unroll
    for (int off = 16; off; off >>= 1) se += __shfl_xor_sync(0xffffffffu, se, off);
    float lse = mx + __logf(se);
    out[n*40 + l] = v0 - lse;
    if (l < 8) out[n*40 + 32 + l] = v1 - lse;
}

// ------------------------- launch --------------------------------------------
extern "C" void kernel_launch(void* const* d_in, const int* in_sizes, int n_in,
                              void* d_out, int out_size){
    const float* x     = (const float*)d_in[0];
    const int*   ei    = (const int*)  d_in[1];
    const float* W1    = (const float*)d_in[2];
    const float* as1w  = (const float*)d_in[3];
    const float* ad1w  = (const float*)d_in[4];
    const float* b1    = (const float*)d_in[5];
    const float* W2    = (const float*)d_in[6];
    const float* as2w  = (const float*)d_in[7];
    const float* ad2w  = (const float*)d_in[8];
    const float* b2    = (const float*)d_in[9];
    float*       out   = (float*)d_out;

    k_prep<<<(F_IN*HD + 255)/256, 256>>>(W1, W2);

    // layer 1
    k_gemm1<<<(N_NODES + 127)/128, 256>>>(x, as1w, ad1w);
    k_eagg1<<<(N_EDGES*16)/256, 256>>>(ei);

    // layer 2 (fin1 fused into gemm2 loader)
    k_gemm2<<<(N_NODES + 63)/64, 256>>>(as2w, ad2w, b1);
    k_eagg2<<<(N_EDGES*10)/320, 320>>>(ei);
    k_fin2 <<<(N_NODES*32 + 255)/256, 256>>>(b2, out);
}

// round 12
// speedup vs baseline: 1.0946x; 1.0946x over previous
#include <cuda_runtime.h>
#include <cuda_bf16.h>
#include <math.h>
#include <stdint.h>

#define N_NODES 100000
#define N_EDGES 1600000
#define F_IN    512
#define HD      64
#define NH      8
#define C_OUT   40
#define NB_SCAN 391            // ceil(N_NODES/256)

typedef unsigned long long ull;

// ------------------------- scratch (device globals; no mallocs) -------------
__device__ float    g_h1  [N_NODES*HD];    // layer1 projection
__device__ float    g_h1f [N_NODES*HD];    // layer1 output (post softmax+ELU)
__device__ float2   g_e1s [N_NODES*NH];    // (exp(as), exp(0.2 as))
__device__ float2   g_e1d [N_NODES*NH];
__device__ float    g_h2  [N_NODES*C_OUT];
__device__ float2   g_e2s [N_NODES];
__device__ float2   g_e2d [N_NODES];
__device__ float2   g_Wp2[32*40];
__device__ __nv_bfloat16 g_W1thi[HD*F_IN];
__device__ __nv_bfloat16 g_W1tlo[HD*F_IN];
// CSR build
__device__ int      g_deg [N_NODES];
__device__ int      g_loc [N_NODES];
__device__ int      g_bsum[512];
__device__ int      g_bpre[512];
__device__ int      g_off [N_NODES+1];
__device__ int      g_cur [N_NODES];
__device__ int      g_csr [N_EDGES];

// ------------------------- helpers ------------------------------------------
__device__ __forceinline__ ull ffma2(ull a, ull b, ull c) {
    ull d;
    asm("fma.rn.f32x2 %0, %1, %2, %3;" : "=l"(d) : "l"(a), "l"(b), "l"(c));
    return d;
}
__device__ __forceinline__ float lo32(ull v){ return __uint_as_float((unsigned)(v & 0xffffffffull)); }
__device__ __forceinline__ float hi32(ull v){ return __uint_as_float((unsigned)(v >> 32)); }
__device__ __forceinline__ float elu1(float x){ return x > 0.f ? x : __expf(x) - 1.f; }
__device__ __forceinline__ float edge_exp(float2 ea, float2 eb){
    float p = ea.x * eb.x;
    return p > 1.f ? p : ea.y * eb.y;
}
__device__ __forceinline__ uint32_t smem_u32(const void* p){
    uint32_t a;
    asm("{ .reg .u64 t; cvta.to.shared.u64 t, %1; cvt.u32.u64 %0, t; }" : "=r"(a) : "l"(p));
    return a;
}
__device__ __forceinline__ unsigned pack_bf16(__nv_bfloat16 a, __nv_bfloat16 b){
    return (unsigned)__bfloat16_as_ushort(a) | ((unsigned)__bfloat16_as_ushort(b) << 16);
}
__device__ __forceinline__ void ldsm4(unsigned* r, uint32_t addr){
    asm volatile("ldmatrix.sync.aligned.m8n8.x4.shared.b16 {%0,%1,%2,%3}, [%4];"
        : "=r"(r[0]), "=r"(r[1]), "=r"(r[2]), "=r"(r[3]) : "r"(addr));
}
__device__ __forceinline__ void mma16816(float* c, const unsigned* a, unsigned b0, unsigned b1){
    asm volatile("mma.sync.aligned.m16n8k16.row.col.f32.bf16.bf16.f32 "
        "{%0,%1,%2,%3}, {%4,%5,%6,%7}, {%8,%9}, {%0,%1,%2,%3};"
        : "+f"(c[0]), "+f"(c[1]), "+f"(c[2]), "+f"(c[3])
        : "r"(a[0]), "r"(a[1]), "r"(a[2]), "r"(a[3]), "r"(b0), "r"(b1));
}

// ------------------------- prep: weights + zero degree ----------------------
__global__ void k_prep(const float* __restrict__ W1, const float* __restrict__ W2){
    int i = blockIdx.x*blockDim.x + threadIdx.x;
    if (i < F_IN*HD){
        int k = i >> 6, n = i & 63;
        float v = W1[i];
        __nv_bfloat16 h = __float2bfloat16_rn(v);
        float lo = v - __bfloat162float(h);
        g_W1thi[n*F_IN + k] = h;
        g_W1tlo[n*F_IN + k] = __float2bfloat16_rn(lo);
    }
    if (i < 32*40){
        int kk = i / 40, c = i - kk*40;
        g_Wp2[i] = make_float2(W2[(2*kk)*40 + c], W2[(2*kk+1)*40 + c]);
    }
    for (int j = i; j < N_NODES; j += 32768) g_deg[j] = 0;
}

// ------------------------- CSR build ----------------------------------------
__global__ void k_hist(const int* __restrict__ ei){
    int e = blockIdx.x*blockDim.x + threadIdx.x;
    if (e < N_EDGES) atomicAdd(&g_deg[ei[N_EDGES + e]], 1);
}
__global__ void k_scan1(){
    __shared__ int sm[256];
    int t = threadIdx.x, i = blockIdx.x*256 + t;
    int v = (i < N_NODES) ? g_deg[i] : 0;
    sm[t] = v; __syncthreads();
    #pragma unroll
    for (int off = 1; off < 256; off <<= 1){
        int add = (t >= off) ? sm[t-off] : 0;
        __syncthreads(); sm[t] += add; __syncthreads();
    }
    if (i < N_NODES) g_loc[i] = sm[t] - v;
    if (t == 255) g_bsum[blockIdx.x] = sm[255];
}
__global__ void k_scan2(){
    __shared__ int sm[512];
    int t = threadIdx.x;
    int v = (t < NB_SCAN) ? g_bsum[t] : 0;
    sm[t] = v; __syncthreads();
    #pragma unroll
    for (int off = 1; off < 512; off <<= 1){
        int add = (t >= off) ? sm[t-off] : 0;
        __syncthreads(); sm[t] += add; __syncthreads();
    }
    if (t < NB_SCAN) g_bpre[t] = sm[t] - v;
}
__global__ void k_scan3(){
    int i = blockIdx.x*256 + threadIdx.x;
    if (i < N_NODES){
        int o = g_loc[i] + g_bpre[blockIdx.x];
        g_off[i] = o;
        g_cur[i] = o;
    }
    if (i == 0) g_off[N_NODES] = N_EDGES;
}
__global__ void k_scatter(const int* __restrict__ ei){
    int e = blockIdx.x*blockDim.x + threadIdx.x;
    if (e >= N_EDGES) return;
    int s = ei[e], d = ei[N_EDGES + e];
    int pos = atomicAdd(&g_cur[d], 1);
    g_csr[pos] = s;
}

// ------------------------- GEMM1: mma.sync bf16 2-term split ----------------
__global__ void __launch_bounds__(256) k_gemm1(const float* __restrict__ x,
                                               const float* __restrict__ aw_s,
                                               const float* __restrict__ aw_d){
    __shared__ __align__(16) unsigned char sAhi[128*80];
    __shared__ __align__(16) unsigned char sAlo[128*80];
    __shared__ __align__(16) unsigned char sWhi[64*80];
    __shared__ __align__(16) unsigned char sWlo[64*80];

    int tid = threadIdx.x, w = tid >> 5, l = tid & 31;
    int mg = w >> 1, ng = w & 1;
    int row0 = blockIdx.x * 128;

    uint32_t aAhi = smem_u32(sAhi), aAlo = smem_u32(sAlo);
    uint32_t aWhi = smem_u32(sWhi), aWlo = smem_u32(sWlo);

    float acc[2][4][4];
    #pragma unroll
    for (int a=0;a<2;a++) for (int b=0;b<4;b++) for (int c=0;c<4;c++) acc[a][b][c]=0.f;

    for (int ch = 0; ch < 16; ++ch){
        int k0 = ch * 32;
        __syncthreads();
        #pragma unroll
        for (int j = 0; j < 4; ++j){
            int idx = tid + 256*j;
            int row = idx >> 3, kq = idx & 7;
            int gr = row0 + row;
            float4 v = make_float4(0.f,0.f,0.f,0.f);
            if (gr < N_NODES) v = *(const float4*)(x + (size_t)gr*F_IN + k0 + kq*4);
            __nv_bfloat16 h0=__float2bfloat16_rn(v.x), h1=__float2bfloat16_rn(v.y),
                          h2=__float2bfloat16_rn(v.z), h3=__float2bfloat16_rn(v.w);
            uint2 hp, lp;
            hp.x = pack_bf16(h0, h1); hp.y = pack_bf16(h2, h3);
            lp.x = pack_bf16(__float2bfloat16_rn(v.x - __bfloat162float(h0)),
                             __float2bfloat16_rn(v.y - __bfloat162float(h1)));
            lp.y = pack_bf16(__float2bfloat16_rn(v.z - __bfloat162float(h2)),
                             __float2bfloat16_rn(v.w - __bfloat162float(h3)));
            *(uint2*)(sAhi + row*80 + kq*8) = hp;
            *(uint2*)(sAlo + row*80 + kq*8) = lp;
        }
        #pragma unroll
        for (int j = 0; j < 2; ++j){
            int idx = tid + 256*j;
            int n = idx >> 3, kq = idx & 7;
            *(uint2*)(sWhi + n*80 + kq*8) = *(const uint2*)(g_W1thi + n*F_IN + k0 + kq*4);
            *(uint2*)(sWlo + n*80 + kq*8) = *(const uint2*)(g_W1tlo + n*F_IN + k0 + kq*4);
        }
        __syncthreads();
        int g = l >> 3, i = l & 7;
        #pragma unroll
        for (int ks = 0; ks < 2; ++ks){
            int kb = ks*32;
            unsigned ah[2][4], al[2][4], bh[2][4], bl[2][4];
            #pragma unroll
            for (int mt = 0; mt < 2; ++mt){
                int rl = mg*32 + mt*16 + i + ((g & 1) ? 8 : 0);
                int co = kb + ((g & 2) ? 16 : 0);
                ldsm4(ah[mt], aAhi + rl*80 + co);
                ldsm4(al[mt], aAlo + rl*80 + co);
            }
            #pragma unroll
            for (int np = 0; np < 2; ++np){
                int nl = ng*32 + np*16 + i + ((g & 2) ? 8 : 0);
                int co = kb + ((g & 1) ? 16 : 0);
                ldsm4(bh[np], aWhi + nl*80 + co);
                ldsm4(bl[np], aWlo + nl*80 + co);
            }
            #pragma unroll
            for (int mt = 0; mt < 2; ++mt)
                #pragma unroll
                for (int np = 0; np < 2; ++np){
                    mma16816(acc[mt][2*np],   ah[mt], bh[np][0], bh[np][1]);
                    mma16816(acc[mt][2*np+1], ah[mt], bh[np][2], bh[np][3]);
                    mma16816(acc[mt][2*np],   ah[mt], bl[np][0], bl[np][1]);
                    mma16816(acc[mt][2*np+1], ah[mt], bl[np][2], bl[np][3]);
                    mma16816(acc[mt][2*np],   al[mt], bh[np][0], bh[np][1]);
                    mma16816(acc[mt][2*np+1], al[mt], bh[np][2], bh[np][3]);
                }
        }
    }

    // ---- epilogue: h1 + exp-factor tables ----
    int q = l & 3;
    #pragma unroll
    for (int mt = 0; mt < 2; ++mt)
        #pragma unroll
        for (int half = 0; half < 2; ++half){
            int gr = row0 + mg*32 + mt*16 + half*8 + (l >> 2);
            bool ok = gr < N_NODES;
            float hs[4], hd[4];
            #pragma unroll
            for (int nt = 0; nt < 4; ++nt){
                float c0 = acc[mt][nt][half*2], c1 = acc[mt][nt][half*2+1];
                if (ok){
                    int col = ng*32 + nt*8 + 2*q;
                    *(float2*)(g_h1 + gr*64 + col) = make_float2(c0, c1);
                }
                int head = 4*ng + nt;
                hs[nt] = c0*__ldg(aw_s + head*8 + 2*q) + c1*__ldg(aw_s + head*8 + 2*q + 1);
                hd[nt] = c0*__ldg(aw_d + head*8 + 2*q) + c1*__ldg(aw_d + head*8 + 2*q + 1);
            }
            #pragma unroll
            for (int nt = 0; nt < 4; ++nt){
                hs[nt] += __shfl_xor_sync(0xffffffffu, hs[nt], 1);
                hs[nt] += __shfl_xor_sync(0xffffffffu, hs[nt], 2);
                hd[nt] += __shfl_xor_sync(0xffffffffu, hd[nt], 1);
                hd[nt] += __shfl_xor_sync(0xffffffffu, hd[nt], 2);
            }
            if (ok){
                float vs = (q==0)?hs[0]:(q==1)?hs[1]:(q==2)?hs[2]:hs[3];
                float vd = (q==0)?hd[0]:(q==1)?hd[1]:(q==2)?hd[2]:hd[3];
                int slot = gr*8 + 4*ng + q;
                g_e1s[slot] = make_float2(__expf(vs), __expf(0.2f*vs));
                g_e1d[slot] = make_float2(__expf(vd), __expf(0.2f*vd));
            }
        }
}

// ------------------------- layer1 CSR gather (warp per node) ----------------
// Fuses aggregate + denominator + self-loop + normalize + bias + ELU -> h1f.
__global__ void __launch_bounds__(256) k_gat1(const float* __restrict__ b1){
    int tid  = threadIdx.x;
    int node = blockIdx.x*8 + (tid >> 5);
    int l    = tid & 31;
    int h    = l >> 2;                       // head of cols (2l, 2l+1)
    if (node >= N_NODES) return;

    float2 ed = g_e1d[node*8 + h];
    int beg = g_off[node];
    int deg = g_off[node+1] - beg;

    int sv0 = 0, sv1 = 0;
    if (l      < deg) sv0 = g_csr[beg + l];
    if (32 + l < deg) sv1 = g_csr[beg + 32 + l];

    float2 acc = make_float2(0.f, 0.f);
    float  den = 0.f;

    int nin = deg < 64 ? deg : 64;
    for (int i = 0; i < nin; ++i){
        int s = __shfl_sync(0xffffffffu, (i < 32) ? sv0 : sv1, i & 31);
        float2 es = g_e1s[s*8 + h];
        float p  = es.x * ed.x;
        float ee = p > 1.f ? p : es.y * ed.y;
        float2 hv = *(const float2*)(g_h1 + s*64 + 2*l);
        acc.x += ee*hv.x; acc.y += ee*hv.y;
        den   += ee;                         // same value across the quad
    }
    for (int i = 64; i < deg; ++i){          // essentially never taken
        int s = g_csr[beg + i];
        float2 es = g_e1s[s*8 + h];
        float p  = es.x * ed.x;
        float ee = p > 1.f ? p : es.y * ed.y;
        float2 hv = *(const float2*)(g_h1 + s*64 + 2*l);
        acc.x += ee*hv.x; acc.y += ee*hv.y;
        den   += ee;
    }

    // self-loop + normalize + bias + ELU
    float2 esn = g_e1s[node*8 + h];
    float p  = esn.x * ed.x;
    float ws = p > 1.f ? p : esn.y * ed.y;
    float inv = 1.f / (den + ws + 1e-16f);
    float2 hvn = *(const float2*)(g_h1 + node*64 + 2*l);
    float2 bb  = *(const float2*)(b1 + 2*l);
    float2 o;
    o.x = elu1((acc.x + ws*hvn.x)*inv + bb.x);
    o.y = elu1((acc.y + ws*hvn.y)*inv + bb.y);
    *(float2*)(g_h1f + node*64 + 2*l) = o;
}

// ------------------------- GEMM2 (simple h1f loader) ------------------------
__global__ void __launch_bounds__(256) k_gemm2(const float* __restrict__ aw_s,
                                               const float* __restrict__ aw_d){
    __shared__ float sx[64*64];
    int row0 = blockIdx.x * 64;
    int tid  = threadIdx.x;

    float4* s4 = (float4*)sx;
    const float4* xg = (const float4*)g_h1f;
    #pragma unroll
    for (int i = 0; i < 4; ++i){
        int idx  = tid + 256*i;
        int grow = row0 + (idx >> 4);
        float4 v = make_float4(0.f,0.f,0.f,0.f);
        if (grow < N_NODES) v = xg[(size_t)grow*16 + (idx & 15)];
        s4[idx] = v;
    }
    __syncthreads();

    int w = tid >> 5, l = tid & 31;
    ull acc0[8], acc1[8];
    #pragma unroll
    for (int r = 0; r < 8; ++r){ acc0[r] = 0ull; acc1[r] = 0ull; }

    const ull* sb = (const ull*)sx;
    const ull* wp = (const ull*)g_Wp2;
    #pragma unroll 4
    for (int kk = 0; kk < 32; kk += 2){
        ull w0a = wp[kk*40 + l];
        ull w1a = (l < 8) ? wp[kk*40 + 32 + l] : 0ull;
        ull w0b = wp[(kk+1)*40 + l];
        ull w1b = (l < 8) ? wp[(kk+1)*40 + 32 + l] : 0ull;
        #pragma unroll
        for (int r = 0; r < 8; ++r){
            const ull* srow = sb + (8*w + r)*32;
            ulonglong2 xv = *(const ulonglong2*)(srow + kk);
            acc0[r] = ffma2(xv.x, w0a, acc0[r]);
            acc1[r] = ffma2(xv.x, w1a, acc1[r]);
            acc0[r] = ffma2(xv.y, w0b, acc0[r]);
            acc1[r] = ffma2(xv.y, w1b, acc1[r]);
        }
    }

    #pragma unroll
    for (int r = 0; r < 8; ++r){
        int row = row0 + 8*w + r;
        bool valid = row < N_NODES;
        float o0 = lo32(acc0[r]) + hi32(acc0[r]);
        float o1 = lo32(acc1[r]) + hi32(acc1[r]);
        if (valid){
            g_h2[row*40 + l] = o0;
            if (l < 8) g_h2[row*40 + 32 + l] = o1;
        }
        float ps = o0*aw_s[l] + ((l < 8) ? o1*aw_s[32+l] : 0.f);
        float pd = o0*aw_d[l] + ((l < 8) ? o1*aw_d[32+l] : 0.f);
        #pragma unroll
        for (int off = 16; off; off >>= 1){
            ps += __shfl_xor_sync(0xffffffffu, ps, off);
            pd += __shfl_xor_sync(0xffffffffu, pd, off);
        }
        if (l == 0 && valid){
            g_e2s[row] = make_float2(__expf(ps), __expf(0.2f*ps));
            g_e2d[row] = make_float2(__expf(pd), __expf(0.2f*pd));
        }
    }
}

// ------------------------- layer2 CSR gather + log_softmax ------------------
// Warp per node; lanes 0-9 hold float4 (40 cols). Writes final output.
__global__ void __launch_bounds__(256) k_gat2(const float* __restrict__ b2,
                                              float* __restrict__ out){
    int tid  = threadIdx.x;
    int node = blockIdx.x*8 + (tid >> 5);
    int l    = tid & 31;
    if (node >= N_NODES) return;

    float2 ed = g_e2d[node];
    int beg = g_off[node];
    int deg = g_off[node+1] - beg;

    int sv0 = 0, sv1 = 0;
    if (l      < deg) sv0 = g_csr[beg + l];
    if (32 + l < deg) sv1 = g_csr[beg + 32 + l];

    float4 acc = make_float4(0.f,0.f,0.f,0.f);
    float  den = 0.f;

    int nin = deg < 64 ? deg : 64;
    for (int i = 0; i < nin; ++i){
        int s = __shfl_sync(0xffffffffu, (i < 32) ? sv0 : sv1, i & 31);
        float2 es = g_e2s[s];
        float p  = es.x * ed.x;
        float ee = p > 1.f ? p : es.y * ed.y;
        den += ee;
        if (l < 10){
            float4 hv = ((const float4*)g_h2)[s*10 + l];
            acc.x += ee*hv.x; acc.y += ee*hv.y; acc.z += ee*hv.z; acc.w += ee*hv.w;
        }
    }
    for (int i = 64; i < deg; ++i){
        int s = g_csr[beg + i];
        float2 es = g_e2s[s];
        float p  = es.x * ed.x;
        float ee = p > 1.f ? p : es.y * ed.y;
        den += ee;
        if (l < 10){
            float4 hv = ((const float4*)g_h2)[s*10 + l];
            acc.x += ee*hv.x; acc.y += ee*hv.y; acc.z += ee*hv.z; acc.w += ee*hv.w;
        }
    }

    float2 esn = g_e2s[node];
    float p  = esn.x * ed.x;
    float ws = p > 1.f ? p : esn.y * ed.y;
    float inv = 1.f / (den + ws + 1e-16f);

    float4 v = make_float4(-INFINITY,-INFINITY,-INFINITY,-INFINITY);
    if (l < 10){
        float4 hvn = ((const float4*)g_h2)[node*10 + l];
        float4 bb  = ((const float4*)b2)[l];
        v.x = (acc.x + ws*hvn.x)*inv + bb.x;
        v.y = (acc.y + ws*hvn.y)*inv + bb.y;
        v.z = (acc.z + ws*hvn.z)*inv + bb.z;
        v.w = (acc.w + ws*hvn.w)*inv + bb.w;
    }
    float mx = fmaxf(fmaxf(v.x, v.y), fmaxf(v.z, v.w));
    #pragma unroll
    for (int off = 16; off; off >>= 1) mx = fmaxf(mx, __shfl_xor_sync(0xffffffffu, mx, off));
    float se = 0.f;
    if (l < 10)
        se = __expf(v.x - mx) + __expf(v.y - mx) + __expf(v.z - mx) + __expf(v.w - mx);
    #pragma unroll
    for (int off = 16; off; off >>= 1) se += __shfl_xor_sync(0xffffffffu, se, off);
    float lse = mx + __logf(se);
    if (l < 10){
        float4 o = make_float4(v.x - lse, v.y - lse, v.z - lse, v.w - lse);
        ((float4*)out)[node*10 + l] = o;
    }
}

// ------------------------- launch --------------------------------------------
extern "C" void kernel_launch(void* const* d_in, const int* in_sizes, int n_in,
                              void* d_out, int out_size){
    const float* x     = (const float*)d_in[0];
    const int*   ei    = (const int*)  d_in[1];
    const float* W1    = (const float*)d_in[2];
    const float* as1w  = (const float*)d_in[3];
    const float* ad1w  = (const float*)d_in[4];
    const float* b1    = (const float*)d_in[5];
    const float* W2    = (const float*)d_in[6];
    const float* as2w  = (const float*)d_in[7];
    const float* ad2w  = (const float*)d_in[8];
    const float* b2    = (const float*)d_in[9];
    float*       out   = (float*)d_out;

    // weight prep + degree zero
    k_prep<<<128, 256>>>(W1, W2);
    // CSR build (dst-sorted), reused by both layers
    k_hist   <<<(N_EDGES + 255)/256, 256>>>(ei);
    k_scan1  <<<NB_SCAN, 256>>>();
    k_scan2  <<<1, 512>>>();
    k_scan3  <<<NB_SCAN, 256>>>();
    k_scatter<<<(N_EDGES + 255)/256, 256>>>(ei);

    // layer 1
    k_gemm1<<<(N_NODES + 127)/128, 256>>>(x, as1w, ad1w);
    k_gat1 <<<(N_NODES + 7)/8, 256>>>(b1);

    // layer 2
    k_gemm2<<<(N_NODES + 63)/64, 256>>>(as2w, ad2w);
    k_gat2 <<<(N_NODES + 7)/8, 256>>>(b2, out);
}

// round 17
// speedup vs baseline: 1.1173x; 1.0208x over previous
#include <cuda_runtime.h>
#include <cuda_bf16.h>
#include <math.h>
#include <stdint.h>

#define N_NODES 100000
#define N_EDGES 1600000
#define F_IN    512
#define HD      64
#define NH      8
#define C_OUT   40
#define NB_SCAN 391            // ceil(N_NODES/256)

// gemm1 double-buffer smem layout (bytes)
#define ABUF   10240           // 128 rows * 80B  (one A plane)
#define WBUF   5120            // 64 rows * 80B   (one W plane)
#define OFF_AHI 0
#define OFF_ALO ABUF
#define OFF_WHI (2*ABUF)
#define OFF_WLO (2*ABUF + WBUF)
#define BUFSZ  (2*ABUF + 2*WBUF)   // 30720
#define G1_SMEM (2*BUFSZ)          // 61440

typedef unsigned long long ull;

// ------------------------- scratch (device globals; no mallocs) -------------
__device__ float    g_h1  [N_NODES*HD];    // layer1 projection
__device__ float    g_h1f [N_NODES*HD];    // layer1 output (post softmax+ELU)
__device__ float2   g_e1s [N_NODES*NH];    // (exp(as), exp(0.2 as))
__device__ float2   g_e1d [N_NODES*NH];
__device__ float    g_h2  [N_NODES*C_OUT];
__device__ float2   g_e2s [N_NODES];
__device__ float2   g_e2d [N_NODES];
__device__ float2   g_Wp2[32*40];
__device__ __nv_bfloat16 g_W1thi[HD*F_IN];
__device__ __nv_bfloat16 g_W1tlo[HD*F_IN];
// CSR build
__device__ int      g_deg [N_NODES];
__device__ int      g_loc [N_NODES];
__device__ int      g_bsum[512];
__device__ int      g_bpre[512];
__device__ int      g_off [N_NODES+1];
__device__ int      g_cur [N_NODES];
__device__ int      g_csr [N_EDGES];

// ------------------------- helpers ------------------------------------------
__device__ __forceinline__ ull ffma2(ull a, ull b, ull c) {
    ull d;
    asm("fma.rn.f32x2 %0, %1, %2, %3;" : "=l"(d) : "l"(a), "l"(b), "l"(c));
    return d;
}
__device__ __forceinline__ float lo32(ull v){ return __uint_as_float((unsigned)(v & 0xffffffffull)); }
__device__ __forceinline__ float hi32(ull v){ return __uint_as_float((unsigned)(v >> 32)); }
__device__ __forceinline__ float elu1(float x){ return x > 0.f ? x : __expf(x) - 1.f; }
__device__ __forceinline__ float edge_exp(float2 ea, float2 eb){
    float p = ea.x * eb.x;
    return p > 1.f ? p : ea.y * eb.y;
}
__device__ __forceinline__ uint32_t smem_u32(const void* p){
    uint32_t a;
    asm("{ .reg .u64 t; cvta.to.shared.u64 t, %1; cvt.u32.u64 %0, t; }" : "=r"(a) : "l"(p));
    return a;
}
__device__ __forceinline__ unsigned pack_bf16(__nv_bfloat16 a, __nv_bfloat16 b){
    return (unsigned)__bfloat16_as_ushort(a) | ((unsigned)__bfloat16_as_ushort(b) << 16);
}
__device__ __forceinline__ void ldsm4(unsigned* r, uint32_t addr){
    asm volatile("ldmatrix.sync.aligned.m8n8.x4.shared.b16 {%0,%1,%2,%3}, [%4];"
        : "=r"(r[0]), "=r"(r[1]), "=r"(r[2]), "=r"(r[3]) : "r"(addr));
}
__device__ __forceinline__ void mma16816(float* c, const unsigned* a, unsigned b0, unsigned b1){
    asm volatile("mma.sync.aligned.m16n8k16.row.col.f32.bf16.bf16.f32 "
        "{%0,%1,%2,%3}, {%4,%5,%6,%7}, {%8,%9}, {%0,%1,%2,%3};"
        : "+f"(c[0]), "+f"(c[1]), "+f"(c[2]), "+f"(c[3])
        : "r"(a[0]), "r"(a[1]), "r"(a[2]), "r"(a[3]), "r"(b0), "r"(b1));
}

// ------------------------- prep: weights + zero degree ----------------------
__global__ void k_prep(const float* __restrict__ W1, const float* __restrict__ W2){
    int i = blockIdx.x*blockDim.x + threadIdx.x;
    if (i < F_IN*HD){
        int k = i >> 6, n = i & 63;
        float v = W1[i];
        __nv_bfloat16 h = __float2bfloat16_rn(v);
        float lo = v - __bfloat162float(h);
        g_W1thi[n*F_IN + k] = h;
        g_W1tlo[n*F_IN + k] = __float2bfloat16_rn(lo);
    }
    if (i < 32*40){
        int kk = i / 40, c = i - kk*40;
        g_Wp2[i] = make_float2(W2[(2*kk)*40 + c], W2[(2*kk+1)*40 + c]);
    }
    for (int j = i; j < N_NODES; j += 32768) g_deg[j] = 0;
}

// ------------------------- CSR build ----------------------------------------
__global__ void k_hist(const int* __restrict__ ei){
    int e = blockIdx.x*blockDim.x + threadIdx.x;
    if (e < N_EDGES) atomicAdd(&g_deg[ei[N_EDGES + e]], 1);
}
__global__ void k_scan1(){
    __shared__ int sm[256];
    int t = threadIdx.x, i = blockIdx.x*256 + t;
    int v = (i < N_NODES) ? g_deg[i] : 0;
    sm[t] = v; __syncthreads();
    #pragma unroll
    for (int off = 1; off < 256; off <<= 1){
        int add = (t >= off) ? sm[t-off] : 0;
        __syncthreads(); sm[t] += add; __syncthreads();
    }
    if (i < N_NODES) g_loc[i] = sm[t] - v;
    if (t == 255) g_bsum[blockIdx.x] = sm[255];
}
__global__ void k_scan2(){
    __shared__ int sm[512];
    int t = threadIdx.x;
    int v = (t < NB_SCAN) ? g_bsum[t] : 0;
    sm[t] = v; __syncthreads();
    #pragma unroll
    for (int off = 1; off < 512; off <<= 1){
        int add = (t >= off) ? sm[t-off] : 0;
        __syncthreads(); sm[t] += add; __syncthreads();
    }
    if (t < NB_SCAN) g_bpre[t] = sm[t] - v;
}
__global__ void k_scan3(){
    int i = blockIdx.x*256 + threadIdx.x;
    if (i < N_NODES){
        int o = g_loc[i] + g_bpre[blockIdx.x];
        g_off[i] = o;
        g_cur[i] = o;
    }
    if (i == 0) g_off[N_NODES] = N_EDGES;
}
__global__ void k_scatter(const int* __restrict__ ei){
    int e = blockIdx.x*blockDim.x + threadIdx.x;
    if (e >= N_EDGES) return;
    int s = ei[e], d = ei[N_EDGES + e];
    int pos = atomicAdd(&g_cur[d], 1);
    g_csr[pos] = s;
}

// ------------------------- GEMM1: mma.sync bf16, double-buffered ------------
__global__ void __launch_bounds__(256) k_gemm1(const float* __restrict__ x,
                                               const float* __restrict__ aw_s,
                                               const float* __restrict__ aw_d){
    extern __shared__ __align__(16) unsigned char dyn[];
    int tid = threadIdx.x, w = tid >> 5, l = tid & 31;
    int mg = w >> 1, ng = w & 1;
    int row0 = blockIdx.x * 128;
    uint32_t sbase = smem_u32(dyn);

    float acc[2][4][4];
    #pragma unroll
    for (int a=0;a<2;a++) for (int b=0;b<4;b++) for (int c=0;c<4;c++) acc[a][b][c]=0.f;

    float4 av[4];
    uint2  wh[2], wl[2];

    // load chunk 0
    {
        int k0 = 0;
        #pragma unroll
        for (int j = 0; j < 4; ++j){
            int idx = tid + 256*j;
            int row = idx >> 3, kq = idx & 7;
            int gr = row0 + row;
            av[j] = make_float4(0.f,0.f,0.f,0.f);
            if (gr < N_NODES) av[j] = *(const float4*)(x + (size_t)gr*F_IN + k0 + kq*4);
        }
        #pragma unroll
        for (int j = 0; j < 2; ++j){
            int idx = tid + 256*j;
            int n = idx >> 3, kq = idx & 7;
            wh[j] = *(const uint2*)(g_W1thi + n*F_IN + k0 + kq*4);
            wl[j] = *(const uint2*)(g_W1tlo + n*F_IN + k0 + kq*4);
        }
        unsigned char* buf = dyn;
        #pragma unroll
        for (int j = 0; j < 4; ++j){
            int idx = tid + 256*j;
            int row = idx >> 3, kq = idx & 7;
            float4 v = av[j];
            __nv_bfloat16 h0=__float2bfloat16_rn(v.x), h1=__float2bfloat16_rn(v.y),
                          h2=__float2bfloat16_rn(v.z), h3=__float2bfloat16_rn(v.w);
            uint2 hp, lp;
            hp.x = pack_bf16(h0, h1); hp.y = pack_bf16(h2, h3);
            lp.x = pack_bf16(__float2bfloat16_rn(v.x - __bfloat162float(h0)),
                             __float2bfloat16_rn(v.y - __bfloat162float(h1)));
            lp.y = pack_bf16(__float2bfloat16_rn(v.z - __bfloat162float(h2)),
                             __float2bfloat16_rn(v.w - __bfloat162float(h3)));
            *(uint2*)(buf + OFF_AHI + row*80 + kq*8) = hp;
            *(uint2*)(buf + OFF_ALO + row*80 + kq*8) = lp;
        }
        #pragma unroll
        for (int j = 0; j < 2; ++j){
            int idx = tid + 256*j;
            int n = idx >> 3, kq = idx & 7;
            *(uint2*)(buf + OFF_WHI + n*80 + kq*8) = wh[j];
            *(uint2*)(buf + OFF_WLO + n*80 + kq*8) = wl[j];
        }
    }
    __syncthreads();

    int g = l >> 3, i = l & 7;
    for (int ch = 0; ch < 16; ++ch){
        // issue next chunk's global loads (registers) before compute
        if (ch < 15){
            int k0 = (ch + 1) * 32;
            #pragma unroll
            for (int j = 0; j < 4; ++j){
                int idx = tid + 256*j;
                int row = idx >> 3, kq = idx & 7;
                int gr = row0 + row;
                av[j] = make_float4(0.f,0.f,0.f,0.f);
                if (gr < N_NODES) av[j] = *(const float4*)(x + (size_t)gr*F_IN + k0 + kq*4);
            }
            #pragma unroll
            for (int j = 0; j < 2; ++j){
                int idx = tid + 256*j;
                int n = idx >> 3, kq = idx & 7;
                wh[j] = *(const uint2*)(g_W1thi + n*F_IN + k0 + kq*4);
                wl[j] = *(const uint2*)(g_W1tlo + n*F_IN + k0 + kq*4);
            }
        }

        // compute on buffer ch&1
        {
            uint32_t b = sbase + (ch & 1)*BUFSZ;
            uint32_t aAhi = b + OFF_AHI, aAlo = b + OFF_ALO;
            uint32_t aWhi = b + OFF_WHI, aWlo = b + OFF_WLO;
            #pragma unroll
            for (int ks = 0; ks < 2; ++ks){
                int kb = ks*32;
                unsigned ah[2][4], al[2][4], bh[2][4], bl[2][4];
                #pragma unroll
                for (int mt = 0; mt < 2; ++mt){
                    int rl = mg*32 + mt*16 + i + ((g & 1) ? 8 : 0);
                    int co = kb + ((g & 2) ? 16 : 0);
                    ldsm4(ah[mt], aAhi + rl*80 + co);
                    ldsm4(al[mt], aAlo + rl*80 + co);
                }
                #pragma unroll
                for (int np = 0; np < 2; ++np){
                    int nl = ng*32 + np*16 + i + ((g & 2) ? 8 : 0);
                    int co = kb + ((g & 1) ? 16 : 0);
                    ldsm4(bh[np], aWhi + nl*80 + co);
                    ldsm4(bl[np], aWlo + nl*80 + co);
                }
                #pragma unroll
                for (int mt = 0; mt < 2; ++mt)
                    #pragma unroll
                    for (int np = 0; np < 2; ++np){
                        mma16816(acc[mt][2*np],   ah[mt], bh[np][0], bh[np][1]);
                        mma16816(acc[mt][2*np+1], ah[mt], bh[np][2], bh[np][3]);
                        mma16816(acc[mt][2*np],   ah[mt], bl[np][0], bl[np][1]);
                        mma16816(acc[mt][2*np+1], ah[mt], bl[np][2], bl[np][3]);
                        mma16816(acc[mt][2*np],   al[mt], bh[np][0], bh[np][1]);
                        mma16816(acc[mt][2*np+1], al[mt], bh[np][2], bh[np][3]);
                    }
            }
        }

        // convert + store next chunk into the other buffer
        if (ch < 15){
            unsigned char* buf = dyn + ((ch + 1) & 1)*BUFSZ;
            #pragma unroll
            for (int j = 0; j < 4; ++j){
                int idx = tid + 256*j;
                int row = idx >> 3, kq = idx & 7;
                float4 v = av[j];
                __nv_bfloat16 h0=__float2bfloat16_rn(v.x), h1=__float2bfloat16_rn(v.y),
                              h2=__float2bfloat16_rn(v.z), h3=__float2bfloat16_rn(v.w);
                uint2 hp, lp;
                hp.x = pack_bf16(h0, h1); hp.y = pack_bf16(h2, h3);
                lp.x = pack_bf16(__float2bfloat16_rn(v.x - __bfloat162float(h0)),
                                 __float2bfloat16_rn(v.y - __bfloat162float(h1)));
                lp.y = pack_bf16(__float2bfloat16_rn(v.z - __bfloat162float(h2)),
                                 __float2bfloat16_rn(v.w - __bfloat162float(h3)));
                *(uint2*)(buf + OFF_AHI + row*80 + kq*8) = hp;
                *(uint2*)(buf + OFF_ALO + row*80 + kq*8) = lp;
            }
            #pragma unroll
            for (int j = 0; j < 2; ++j){
                int idx = tid + 256*j;
                int n = idx >> 3, kq = idx & 7;
                *(uint2*)(buf + OFF_WHI + n*80 + kq*8) = wh[j];
                *(uint2*)(buf + OFF_WLO + n*80 + kq*8) = wl[j];
            }
        }
        __syncthreads();
    }

    // ---- epilogue: h1 + exp-factor tables ----
    int q = l & 3;
    #pragma unroll
    for (int mt = 0; mt < 2; ++mt)
        #pragma unroll
        for (int half = 0; half < 2; ++half){
            int gr = row0 + mg*32 + mt*16 + half*8 + (l >> 2);
            bool ok = gr < N_NODES;
            float hs[4], hd[4];
            #pragma unroll
            for (int nt = 0; nt < 4; ++nt){
                float c0 = acc[mt][nt][half*2], c1 = acc[mt][nt][half*2+1];
                if (ok){
                    int col = ng*32 + nt*8 + 2*q;
                    *(float2*)(g_h1 + gr*64 + col) = make_float2(c0, c1);
                }
                int head = 4*ng + nt;
                hs[nt] = c0*__ldg(aw_s + head*8 + 2*q) + c1*__ldg(aw_s + head*8 + 2*q + 1);
                hd[nt] = c0*__ldg(aw_d + head*8 + 2*q) + c1*__ldg(aw_d + head*8 + 2*q + 1);
            }
            #pragma unroll
            for (int nt = 0; nt < 4; ++nt){
                hs[nt] += __shfl_xor_sync(0xffffffffu, hs[nt], 1);
                hs[nt] += __shfl_xor_sync(0xffffffffu, hs[nt], 2);
                hd[nt] += __shfl_xor_sync(0xffffffffu, hd[nt], 1);
                hd[nt] += __shfl_xor_sync(0xffffffffu, hd[nt], 2);
            }
            if (ok){
                float vs = (q==0)?hs[0]:(q==1)?hs[1]:(q==2)?hs[2]:hs[3];
                float vd = (q==0)?hd[0]:(q==1)?hd[1]:(q==2)?hd[2]:hd[3];
                int slot = gr*8 + 4*ng + q;
                g_e1s[slot] = make_float2(__expf(vs), __expf(0.2f*vs));
                g_e1d[slot] = make_float2(__expf(vd), __expf(0.2f*vd));
            }
        }
}

// ------------------------- layer1 CSR gather (warp per node) ----------------
__global__ void __launch_bounds__(256) k_gat1(const float* __restrict__ b1){
    int tid  = threadIdx.x;
    int node = blockIdx.x*8 + (tid >> 5);
    int l    = tid & 31;
    int h    = l >> 2;
    if (node >= N_NODES) return;

    float2 ed = g_e1d[node*8 + h];
    int beg = g_off[node];
    int deg = g_off[node+1] - beg;

    int sv0 = 0, sv1 = 0;
    if (l      < deg) sv0 = g_csr[beg + l];
    if (32 + l < deg) sv1 = g_csr[beg + 32 + l];

    float2 acc = make_float2(0.f, 0.f);
    float  den = 0.f;

    int nin = deg < 64 ? deg : 64;
    for (int i = 0; i < nin; ++i){
        int s = __shfl_sync(0xffffffffu, (i < 32) ? sv0 : sv1, i & 31);
        float2 es = g_e1s[s*8 + h];
        float p  = es.x * ed.x;
        float ee = p > 1.f ? p : es.y * ed.y;
        float2 hv = *(const float2*)(g_h1 + s*64 + 2*l);
        acc.x += ee*hv.x; acc.y += ee*hv.y;
        den   += ee;
    }
    for (int i = 64; i < deg; ++i){
        int s = g_csr[beg + i];
        float2 es = g_e1s[s*8 + h];
        float p  = es.x * ed.x;
        float ee = p > 1.f ? p : es.y * ed.y;
        float2 hv = *(const float2*)(g_h1 + s*64 + 2*l);
        acc.x += ee*hv.x; acc.y += ee*hv.y;
        den   += ee;
    }

    float2 esn = g_e1s[node*8 + h];
    float p  = esn.x * ed.x;
    float ws = p > 1.f ? p : esn.y * ed.y;
    float inv = 1.f / (den + ws + 1e-16f);
    float2 hvn = *(const float2*)(g_h1 + node*64 + 2*l);
    float2 bb  = *(const float2*)(b1 + 2*l);
    float2 o;
    o.x = elu1((acc.x + ws*hvn.x)*inv + bb.x);
    o.y = elu1((acc.y + ws*hvn.y)*inv + bb.y);
    *(float2*)(g_h1f + node*64 + 2*l) = o;
}

// ------------------------- GEMM2 (simple h1f loader) ------------------------
__global__ void __launch_bounds__(256) k_gemm2(const float* __restrict__ aw_s,
                                               const float* __restrict__ aw_d){
    __shared__ float sx[64*64];
    int row0 = blockIdx.x * 64;
    int tid  = threadIdx.x;

    float4* s4 = (float4*)sx;
    const float4* xg = (const float4*)g_h1f;
    #pragma unroll
    for (int i = 0; i < 4; ++i){
        int idx  = tid + 256*i;
        int grow = row0 + (idx >> 4);
        float4 v = make_float4(0.f,0.f,0.f,0.f);
        if (grow < N_NODES) v = xg[(size_t)grow*16 + (idx & 15)];
        s4[idx] = v;
    }
    __syncthreads();

    int w = tid >> 5, l = tid & 31;
    ull acc0[8], acc1[8];
    #pragma unroll
    for (int r = 0; r < 8; ++r){ acc0[r] = 0ull; acc1[r] = 0ull; }

    const ull* sb = (const ull*)sx;
    const ull* wp = (const ull*)g_Wp2;
    #pragma unroll 4
    for (int kk = 0; kk < 32; kk += 2){
        ull w0a = wp[kk*40 + l];
        ull w1a = (l < 8) ? wp[kk*40 + 32 + l] : 0ull;
        ull w0b = wp[(kk+1)*40 + l];
        ull w1b = (l < 8) ? wp[(kk+1)*40 + 32 + l] : 0ull;
        #pragma unroll
        for (int r = 0; r < 8; ++r){
            const ull* srow = sb + (8*w + r)*32;
            ulonglong2 xv = *(const ulonglong2*)(srow + kk);
            acc0[r] = ffma2(xv.x, w0a, acc0[r]);
            acc1[r] = ffma2(xv.x, w1a, acc1[r]);
            acc0[r] = ffma2(xv.y, w0b, acc0[r]);
            acc1[r] = ffma2(xv.y, w1b, acc1[r]);
        }
    }

    #pragma unroll
    for (int r = 0; r < 8; ++r){
        int row = row0 + 8*w + r;
        bool valid = row < N_NODES;
        float o0 = lo32(acc0[r]) + hi32(acc0[r]);
        float o1 = lo32(acc1[r]) + hi32(acc1[r]);
        if (valid){
            g_h2[row*40 + l] = o0;
            if (l < 8) g_h2[row*40 + 32 + l] = o1;
        }
        float ps = o0*aw_s[l] + ((l < 8) ? o1*aw_s[32+l] : 0.f);
        float pd = o0*aw_d[l] + ((l < 8) ? o1*aw_d[32+l] : 0.f);
        #pragma unroll
        for (int off = 16; off; off >>= 1){
            ps += __shfl_xor_sync(0xffffffffu, ps, off);
            pd += __shfl_xor_sync(0xffffffffu, pd, off);
        }
        if (l == 0 && valid){
            g_e2s[row] = make_float2(__expf(ps), __expf(0.2f*ps));
            g_e2d[row] = make_float2(__expf(pd), __expf(0.2f*pd));
        }
    }
}

// ------------------------- layer2 CSR gather + log_softmax ------------------
__global__ void __launch_bounds__(256) k_gat2(const float* __restrict__ b2,
                                              float* __restrict__ out){
    int tid  = threadIdx.x;
    int node = blockIdx.x*8 + (tid >> 5);
    int l    = tid & 31;
    if (node >= N_NODES) return;

    float2 ed = g_e2d[node];
    int beg = g_off[node];
    int deg = g_off[node+1] - beg;

    int sv0 = 0, sv1 = 0;
    if (l      < deg) sv0 = g_csr[beg + l];
    if (32 + l < deg) sv1 = g_csr[beg + 32 + l];

    float4 acc = make_float4(0.f,0.f,0.f,0.f);
    float  den = 0.f;

    int nin = deg < 64 ? deg : 64;
    for (int i = 0; i < nin; ++i){
        int s = __shfl_sync(0xffffffffu, (i < 32) ? sv0 : sv1, i & 31);
        float2 es = g_e2s[s];
        float p  = es.x * ed.x;
        float ee = p > 1.f ? p : es.y * ed.y;
        den += ee;
        if (l < 10){
            float4 hv = ((const float4*)g_h2)[s*10 + l];
            acc.x += ee*hv.x; acc.y += ee*hv.y; acc.z += ee*hv.z; acc.w += ee*hv.w;
        }
    }
    for (int i = 64; i < deg; ++i){
        int s = g_csr[beg + i];
        float2 es = g_e2s[s];
        float p  = es.x * ed.x;
        float ee = p > 1.f ? p : es.y * ed.y;
        den += ee;
        if (l < 10){
            float4 hv = ((const float4*)g_h2)[s*10 + l];
            acc.x += ee*hv.x; acc.y += ee*hv.y; acc.z += ee*hv.z; acc.w += ee*hv.w;
        }
    }

    float2 esn = g_e2s[node];
    float p  = esn.x * ed.x;
    float ws = p > 1.f ? p : esn.y * ed.y;
    float inv = 1.f / (den + ws + 1e-16f);

    float4 v = make_float4(-INFINITY,-INFINITY,-INFINITY,-INFINITY);
    if (l < 10){
        float4 hvn = ((const float4*)g_h2)[node*10 + l];
        float4 bb  = ((const float4*)b2)[l];
        v.x = (acc.x + ws*hvn.x)*inv + bb.x;
        v.y = (acc.y + ws*hvn.y)*inv + bb.y;
        v.z = (acc.z + ws*hvn.z)*inv + bb.z;
        v.w = (acc.w + ws*hvn.w)*inv + bb.w;
    }
    float mx = fmaxf(fmaxf(v.x, v.y), fmaxf(v.z, v.w));
    #pragma unroll
    for (int off = 16; off; off >>= 1) mx = fmaxf(mx, __shfl_xor_sync(0xffffffffu, mx, off));
    float se = 0.f;
    if (l < 10)
        se = __expf(v.x - mx) + __expf(v.y - mx) + __expf(v.z - mx) + __expf(v.w - mx);
    #pragma unroll
    for (int off = 16; off; off >>= 1) se += __shfl_xor_sync(0xffffffffu, se, off);
    float lse = mx + __logf(se);
    if (l < 10){
        float4 o = make_float4(v.x - lse, v.y - lse, v.z - lse, v.w - lse);
        ((float4*)out)[node*10 + l] = o;
    }
}

// ------------------------- launch --------------------------------------------
extern "C" void kernel_launch(void* const* d_in, const int* in_sizes, int n_in,
                              void* d_out, int out_size){
    const float* x     = (const float*)d_in[0];
    const int*   ei    = (const int*)  d_in[1];
    const float* W1    = (const float*)d_in[2];
    const float* as1w  = (const float*)d_in[3];
    const float* ad1w  = (const float*)d_in[4];
    const float* b1    = (const float*)d_in[5];
    const float* W2    = (const float*)d_in[6];
    const float* as2w  = (const float*)d_in[7];
    const float* ad2w  = (const float*)d_in[8];
    const float* b2    = (const float*)d_in[9];
    float*       out   = (float*)d_out;

    cudaFuncSetAttribute(k_gemm1, cudaFuncAttributeMaxDynamicSharedMemorySize, G1_SMEM);

    // weight prep + degree zero
    k_prep<<<128, 256>>>(W1, W2);
    // CSR build (dst-sorted), reused by both layers
    k_hist   <<<(N_EDGES + 255)/256, 256>>>(ei);
    k_scan1  <<<NB_SCAN, 256>>>();
    k_scan2  <<<1, 512>>>();
    k_scan3  <<<NB_SCAN, 256>>>();
    k_scatter<<<(N_EDGES + 255)/256, 256>>>(ei);

    // layer 1
    k_gemm1<<<(N_NODES + 127)/128, 256, G1_SMEM>>>(x, as1w, ad1w);
    k_gat1 <<<(N_NODES + 7)/8, 256>>>(b1);

    // layer 2
    k_gemm2<<<(N_NODES + 63)/64, 256>>>(as2w, ad2w);
    k_gat2 <<<(N_NODES + 7)/8, 256>>>(b2, out);
}